// round 16
// baseline (speedup 1.0000x reference)
#include <cuda_runtime.h>
#include <cuda_fp16.h>

// ---------------------------------------------------------------------------
// GCN_11682311045288: 2-layer GCN via per-launch CSR build + gather aggregation.
// fp16 message table pre-scaled by dinv[src] (CSR = 4B src index per edge);
// fp32 self-loop+bias path; tensor-core (HMMA) GEMM; single-pass
// decoupled-lookback scan for rowptr.
// Inputs: x [N,128] f32, edge_index [2,E] int32, W1[128,64], b1[64], W2[64,64], b2[64]
// Output: z [N,64] f32
// ---------------------------------------------------------------------------

#define MAXN 131072
#define MAXE 2097152
#define F 64
#define F4 (F / 4)    // float4 groups per fp32 row: 16
#define FU4 8         // uint4 (8 halves) groups per fp16 row: 64/8 = 8
#define MAXBLK 512    // max scan blocks

typedef unsigned long long u64;

// Scratch (module-load allocated; allowed).
__device__ uint4  g_xwh[(size_t)MAXN * FU4];  // fp16 dinv[src]*XW table, 128B/row
__device__ float4 g_h [(size_t)MAXN * F4];    // layer-1 result / layer-2 input
__device__ float  g_dinv[MAXN];
__device__ int    g_deg [MAXN];
__device__ int    g_rowptr[MAXN];             // after k_fill: row end
__device__ u64    g_state[MAXBLK];            // lookback: (flag<<62)|sum
__device__ int    g_csr[MAXE];                // src index per edge

__device__ __forceinline__ float2 h2f(unsigned u) {
    __half2 h = *reinterpret_cast<__half2*>(&u);
    return __half22float2(h);
}
__device__ __forceinline__ unsigned s2u(const void* p) {
    return (unsigned)__cvta_generic_to_shared(p);
}
__device__ __forceinline__ void ldmx4(unsigned* r, unsigned addr) {
    asm volatile("ldmatrix.sync.aligned.m8n8.x4.shared.b16 {%0,%1,%2,%3}, [%4];"
                 : "=r"(r[0]), "=r"(r[1]), "=r"(r[2]), "=r"(r[3]) : "r"(addr));
}
__device__ __forceinline__ void ldmx4t(unsigned* r, unsigned addr) {
    asm volatile("ldmatrix.sync.aligned.m8n8.x4.trans.shared.b16 {%0,%1,%2,%3}, [%4];"
                 : "=r"(r[0]), "=r"(r[1]), "=r"(r[2]), "=r"(r[3]) : "r"(addr));
}
__device__ __forceinline__ void mma16816(float* d, const unsigned* a, const unsigned* b) {
    asm volatile(
        "mma.sync.aligned.m16n8k16.row.col.f32.f16.f16.f32 "
        "{%0,%1,%2,%3}, {%4,%5,%6,%7}, {%8,%9}, {%0,%1,%2,%3};"
        : "+f"(d[0]), "+f"(d[1]), "+f"(d[2]), "+f"(d[3])
        : "r"(a[0]), "r"(a[1]), "r"(a[2]), "r"(a[3]), "r"(b[0]), "r"(b[1]));
}

// ---------------------------------------------------------------------------
// Degree count; block 0 also zeroes the lookback state (used by the NEXT
// kernel, ordered by the kernel boundary).
__global__ void k_deg_count(const int* __restrict__ dst, int E) {
    if (blockIdx.x == 0 && threadIdx.x < MAXBLK) {
        g_state[threadIdx.x] = 0ull;
        g_state[threadIdx.x] = 0ull;  // plain store; visible after kernel end
    }
    int i = blockIdx.x * blockDim.x + threadIdx.x;
    int stride = gridDim.x * blockDim.x;
    int E4 = E >> 2;
    const int4* dst4 = (const int4*)dst;
    for (int j = i; j < E4; j += stride) {
        int4 d = dst4[j];
        atomicAdd(&g_deg[d.x], 1);
        atomicAdd(&g_deg[d.y], 1);
        atomicAdd(&g_deg[d.z], 1);
        atomicAdd(&g_deg[d.w], 1);
    }
    for (int j = (E4 << 2) + i; j < E; j += stride)
        atomicAdd(&g_deg[dst[j]], 1);
}

// Single-pass decoupled-lookback exclusive scan of g_deg -> g_rowptr,
// plus dinv = rsqrt(deg+1). All blocks co-resident (grid <= 512 << capacity).
__global__ void k_scan(int n) {
    __shared__ int s[256];
    __shared__ int sbase;
    int b = blockIdx.x;
    int t = threadIdx.x;
    int i = b * 256 + t;
    int v = (i < n) ? g_deg[i] : 0;
    s[t] = v;
    __syncthreads();
    #pragma unroll
    for (int off = 1; off < 256; off <<= 1) {
        int u = (t >= off) ? s[t - off] : 0;
        __syncthreads();
        s[t] += u;
        __syncthreads();
    }
    int incl = s[t];            // inclusive within block
    int agg = s[255];           // block aggregate

    if (t == 0) {
        if (b == 0) {
            atomicExch(&g_state[0], (2ull << 62) | (unsigned)agg);
            sbase = 0;
        } else {
            atomicExch(&g_state[b], (1ull << 62) | (unsigned)agg);
            int excl = 0;
            int j = b - 1;
            while (true) {
                u64 sj = atomicAdd(&g_state[j], 0ull);
                unsigned flag = (unsigned)(sj >> 62);
                if (flag == 0) continue;          // not published yet: spin
                excl += (int)(sj & 0xFFFFFFFFull);
                if (flag == 2u) break;            // inclusive prefix found
                --j;
            }
            atomicExch(&g_state[b], (2ull << 62) | (unsigned)(excl + agg));
            sbase = excl;
        }
    }
    __syncthreads();
    if (i < n) {
        g_rowptr[i] = sbase + incl - v;
        g_dinv[i] = rsqrtf((float)(v + 1));
    }
}

// Counting sort of src by dst. Bumps g_rowptr[d]; afterwards rowptr = row end.
__global__ void k_fill(const int* __restrict__ src,
                       const int* __restrict__ dst, int E) {
    int i = blockIdx.x * blockDim.x + threadIdx.x;
    int stride = gridDim.x * blockDim.x;
    int E4 = E >> 2;
    const int4* src4 = (const int4*)src;
    const int4* dst4 = (const int4*)dst;
    for (int j = i; j < E4; j += stride) {
        int4 s = src4[j];
        int4 d = dst4[j];
        g_csr[atomicAdd(&g_rowptr[d.x], 1)] = s.x;
        g_csr[atomicAdd(&g_rowptr[d.y], 1)] = s.y;
        g_csr[atomicAdd(&g_rowptr[d.z], 1)] = s.z;
        g_csr[atomicAdd(&g_rowptr[d.w], 1)] = s.w;
    }
    for (int j = (E4 << 2) + i; j < E; j += stride)
        g_csr[atomicAdd(&g_rowptr[dst[j]], 1)] = src[j];
}

// ---------------------------------------------------------------------------
// Tensor-core GEMM: 64x64 tile per block, 256 threads = 8 warps.
// Emits: fp16 table row = dinv[r]*acc, fp32 init = dinv[r]^2*acc + bias.
template<int K, bool RELU, bool READ_GH, bool STORE_GH>
__global__ void k_gemm(const float* __restrict__ Xp,
                       const float* __restrict__ W,
                       const float* __restrict__ bias,
                       float* __restrict__ outp,
                       int n)
{
    constexpr int SA = K + 8;
    constexpr int SB = 72;
    __shared__ __half As[64 * SA];
    __shared__ __half Bs[K * SB];

    const float* __restrict__ X = READ_GH ? (const float*)g_h : Xp;
    float* __restrict__ oinit = STORE_GH ? (float*)g_h : outp;
    __half* __restrict__ xwh = (__half*)g_xwh;

    int tid = threadIdx.x;
    int warp = tid >> 5;
    int lane = tid & 31;
    int row0 = blockIdx.x * 64;

    for (int i = tid; i < K * 64; i += 256) {
        int k = i >> 6, nn = i & 63;
        Bs[k * SB + nn] = __float2half_rn(W[i]);
    }
    {
        const int KQ = K / 4;
        for (int i = tid; i < 64 * KQ; i += 256) {
            int r = i / KQ;
            int k4 = (i - r * KQ) * 4;
            int rr = row0 + r;
            float4 v = make_float4(0.f, 0.f, 0.f, 0.f);
            if (rr < n)
                v = ((const float4*)X)[((size_t)rr * K + k4) >> 2];
            if (RELU) {
                v.x = fmaxf(v.x, 0.f); v.y = fmaxf(v.y, 0.f);
                v.z = fmaxf(v.z, 0.f); v.w = fmaxf(v.w, 0.f);
            }
            __half2* dst2 = (__half2*)&As[r * SA + k4];
            dst2[0] = __floats2half2_rn(v.x, v.y);
            dst2[1] = __floats2half2_rn(v.z, v.w);
        }
    }
    __syncthreads();

    const int wr = (warp & 3) * 16;
    const int wc = (warp >> 2) * 32;

    float d[4][4];
    #pragma unroll
    for (int f = 0; f < 4; ++f)
        #pragma unroll
        for (int i = 0; i < 4; ++i) d[f][i] = 0.f;

    unsigned baseA = s2u(&As[(wr + (lane & 15)) * SA + (lane >> 4) * 8]);
    unsigned baseB0 = s2u(&Bs[(lane & 15) * SB + wc + (lane >> 4) * 8]);
    unsigned baseB1 = s2u(&Bs[(lane & 15) * SB + wc + 16 + (lane >> 4) * 8]);

    #pragma unroll
    for (int k0 = 0; k0 < K; k0 += 16) {
        unsigned a[4], b[8];
        ldmx4 (a,     baseA  + k0 * 2);
        ldmx4t(b,     baseB0 + k0 * SB * 2);
        ldmx4t(b + 4, baseB1 + k0 * SB * 2);
        mma16816(d[0], a, b + 0);
        mma16816(d[1], a, b + 2);
        mma16816(d[2], a, b + 4);
        mma16816(d[3], a, b + 6);
    }

    int rA = row0 + wr + (lane >> 2);
    int rB = rA + 8;
    float diA = (rA < n) ? g_dinv[rA] : 0.f;
    float diB = (rB < n) ? g_dinv[rB] : 0.f;
    float sA = diA * diA, sB = diB * diB;
    #pragma unroll
    for (int f = 0; f < 4; ++f) {
        int c = wc + f * 8 + 2 * (lane & 3);
        float b0 = bias[c], b1 = bias[c + 1];
        if (rA < n) {
            *(__half2*)&xwh[(size_t)rA * 64 + c] =
                __floats2half2_rn(diA * d[f][0], diA * d[f][1]);
            float2 o2 = make_float2(fmaf(sA, d[f][0], b0), fmaf(sA, d[f][1], b1));
            *(float2*)&oinit[(size_t)rA * 64 + c] = o2;
        }
        if (rB < n) {
            *(__half2*)&xwh[(size_t)rB * 64 + c] =
                __floats2half2_rn(diB * d[f][2], diB * d[f][3]);
            float2 o2 = make_float2(fmaf(sB, d[f][2], b0), fmaf(sB, d[f][3], b1));
            *(float2*)&oinit[(size_t)rB * 64 + c] = o2;
        }
    }
}

// ---------------------------------------------------------------------------
// Gather aggregation: 8-lane group per node, lane owns 8 features.
// Messages pre-scaled by dinv[src] -> inner loop is pure adds; multiply by
// dinv[node] once at the end, then add the fp32 init row.
template<bool TO_GH>
__global__ void k_aggr(float4* __restrict__ outp, int n)
{
    float4* __restrict__ o = TO_GH ? g_h : outp;
    const uint4* __restrict__ xwh = g_xwh;

    int gtid = blockIdx.x * blockDim.x + threadIdx.x;
    int node = gtid >> 3;
    int lane = threadIdx.x & 7;
    if (node >= n) return;

    int end = g_rowptr[node];
    int deg = g_deg[node];
    int beg = end - deg;

    float acc[8];
    #pragma unroll
    for (int i = 0; i < 8; ++i) acc[i] = 0.f;

    #define ACC_EDGE(q) do {                                                 \
        float2 p0_ = h2f((q).x);                                             \
        float2 p1_ = h2f((q).y);                                             \
        float2 p2_ = h2f((q).z);                                             \
        float2 p3_ = h2f((q).w);                                             \
        acc[0] += p0_.x; acc[1] += p0_.y;                                    \
        acc[2] += p1_.x; acc[3] += p1_.y;                                    \
        acc[4] += p2_.x; acc[5] += p2_.y;                                    \
        acc[6] += p3_.x; acc[7] += p3_.y;                                    \
    } while (0)

    int e = beg;
    for (; e + 4 <= end; e += 4) {
        int s0 = g_csr[e];
        int s1 = g_csr[e + 1];
        int s2 = g_csr[e + 2];
        int s3 = g_csr[e + 3];
        uint4 q0 = __ldcg(xwh + (size_t)s0 * FU4 + lane);
        uint4 q1 = __ldcg(xwh + (size_t)s1 * FU4 + lane);
        uint4 q2 = __ldcg(xwh + (size_t)s2 * FU4 + lane);
        uint4 q3 = __ldcg(xwh + (size_t)s3 * FU4 + lane);
        ACC_EDGE(q0);
        ACC_EDGE(q1);
        ACC_EDGE(q2);
        ACC_EDGE(q3);
    }
    for (; e < end; ++e) {
        uint4 q = __ldcg(xwh + (size_t)g_csr[e] * FU4 + lane);
        ACC_EDGE(q);
    }
    #undef ACC_EDGE

    float dn = g_dinv[node];
    float4* p = o + (size_t)node * F4 + 2 * lane;
    float4 i0 = p[0];
    float4 i1 = p[1];
    i0.x = fmaf(dn, acc[0], i0.x); i0.y = fmaf(dn, acc[1], i0.y);
    i0.z = fmaf(dn, acc[2], i0.z); i0.w = fmaf(dn, acc[3], i0.w);
    i1.x = fmaf(dn, acc[4], i1.x); i1.y = fmaf(dn, acc[5], i1.y);
    i1.z = fmaf(dn, acc[6], i1.z); i1.w = fmaf(dn, acc[7], i1.w);
    p[0] = i0;
    p[1] = i1;
}

// ---------------------------------------------------------------------------
extern "C" void kernel_launch(void* const* d_in, const int* in_sizes, int n_in,
                              void* d_out, int out_size)
{
    const float* x  = (const float*)d_in[0];
    const int*   ei = (const int*)d_in[1];
    const float* W1 = (const float*)d_in[2];
    const float* b1 = (const float*)d_in[3];
    const float* W2 = (const float*)d_in[4];
    const float* b2 = (const float*)d_in[5];
    float* out = (float*)d_out;

    const int IN = 128;
    int N = in_sizes[0] / IN;
    int E = in_sizes[1] / 2;
    const int* src = ei;
    const int* dst = ei + E;

    int nb256 = (N + 255) / 256;
    int gemm_blocks = (N + 63) / 64;
    int edge_blocks = 1184;
    int aggr_blocks = (N + 31) / 32;

    // --- graph preprocessing ---
    void* degptr = nullptr;
    cudaGetSymbolAddress(&degptr, g_deg);
    cudaMemsetAsync(degptr, 0, (size_t)N * sizeof(int));
    k_deg_count<<<edge_blocks, 256>>>(dst, E);
    k_scan<<<nb256, 256>>>(N);
    k_fill<<<edge_blocks, 256>>>(src, dst, E);

    // --- layer 1: init rows -> g_h, aggregate into g_h ---
    k_gemm<128, false, false, true><<<gemm_blocks, 256>>>(x, W1, b1, nullptr, N);
    k_aggr<true><<<aggr_blocks, 256>>>(nullptr, N);

    // --- layer 2: init rows -> out, aggregate into out ---
    k_gemm<64, true, true, false><<<gemm_blocks, 256>>>(nullptr, W2, b2, out, N);
    k_aggr<false><<<aggr_blocks, 256>>>((float4*)out, N);
}

// round 17
// speedup vs baseline: 1.3587x; 1.3587x over previous
#include <cuda_runtime.h>
#include <cuda_fp16.h>

// ---------------------------------------------------------------------------
// GCN_11682311045288: 2-layer GCN via per-launch CSR build + gather aggregation.
// fp16 message table pre-scaled by dinv[src] (CSR = 4B src index per edge);
// fp32 self-loop+bias path; tensor-core (HMMA) GEMM; single-pass
// decoupled-lookback scan for rowptr.
// Inputs: x [N,128] f32, edge_index [2,E] int32, W1[128,64], b1[64], W2[64,64], b2[64]
// Output: z [N,64] f32
// ---------------------------------------------------------------------------

#define MAXN 131072
#define MAXE 2097152
#define F 64
#define F4 (F / 4)    // float4 groups per fp32 row: 16
#define FU4 8         // uint4 (8 halves) groups per fp16 row: 64/8 = 8
#define MAXBLK 512    // max scan blocks

typedef unsigned long long u64;

// Scratch (module-load allocated; allowed).
__device__ uint4  g_xwh[(size_t)MAXN * FU4];  // fp16 dinv[src]*XW table, 128B/row
__device__ float4 g_h [(size_t)MAXN * F4];    // layer-1 result / layer-2 input
__device__ float  g_dinv[MAXN];
__device__ int    g_deg [MAXN];
__device__ int    g_rowptr[MAXN];             // after k_fill: row end
__device__ u64    g_state[MAXBLK];            // lookback: (flag<<62)|sum
__device__ int    g_csr[MAXE];                // src index per edge

__device__ __forceinline__ float2 h2f(unsigned u) {
    __half2 h = *reinterpret_cast<__half2*>(&u);
    return __half22float2(h);
}
__device__ __forceinline__ unsigned s2u(const void* p) {
    return (unsigned)__cvta_generic_to_shared(p);
}
__device__ __forceinline__ void ldmx4(unsigned* r, unsigned addr) {
    asm volatile("ldmatrix.sync.aligned.m8n8.x4.shared.b16 {%0,%1,%2,%3}, [%4];"
                 : "=r"(r[0]), "=r"(r[1]), "=r"(r[2]), "=r"(r[3]) : "r"(addr));
}
__device__ __forceinline__ void ldmx4t(unsigned* r, unsigned addr) {
    asm volatile("ldmatrix.sync.aligned.m8n8.x4.trans.shared.b16 {%0,%1,%2,%3}, [%4];"
                 : "=r"(r[0]), "=r"(r[1]), "=r"(r[2]), "=r"(r[3]) : "r"(addr));
}
__device__ __forceinline__ void mma16816(float* d, const unsigned* a, const unsigned* b) {
    asm volatile(
        "mma.sync.aligned.m16n8k16.row.col.f32.f16.f16.f32 "
        "{%0,%1,%2,%3}, {%4,%5,%6,%7}, {%8,%9}, {%0,%1,%2,%3};"
        : "+f"(d[0]), "+f"(d[1]), "+f"(d[2]), "+f"(d[3])
        : "r"(a[0]), "r"(a[1]), "r"(a[2]), "r"(a[3]), "r"(b[0]), "r"(b[1]));
}

// ---------------------------------------------------------------------------
// Degree count; block 0 also zeroes the lookback state (used by the NEXT
// kernel, ordered by the kernel boundary).
__global__ void k_deg_count(const int* __restrict__ dst, int E) {
    if (blockIdx.x == 0 && threadIdx.x < MAXBLK) {
        g_state[threadIdx.x] = 0ull;
        g_state[threadIdx.x] = 0ull;  // plain store; visible after kernel end
    }
    int i = blockIdx.x * blockDim.x + threadIdx.x;
    int stride = gridDim.x * blockDim.x;
    int E4 = E >> 2;
    const int4* dst4 = (const int4*)dst;
    for (int j = i; j < E4; j += stride) {
        int4 d = dst4[j];
        atomicAdd(&g_deg[d.x], 1);
        atomicAdd(&g_deg[d.y], 1);
        atomicAdd(&g_deg[d.z], 1);
        atomicAdd(&g_deg[d.w], 1);
    }
    for (int j = (E4 << 2) + i; j < E; j += stride)
        atomicAdd(&g_deg[dst[j]], 1);
}

// Single-pass decoupled-lookback exclusive scan of g_deg -> g_rowptr,
// plus dinv = rsqrt(deg+1). All blocks co-resident (grid <= 512 << capacity).
__global__ void k_scan(int n) {
    __shared__ int s[256];
    __shared__ int sbase;
    int b = blockIdx.x;
    int t = threadIdx.x;
    int i = b * 256 + t;
    int v = (i < n) ? g_deg[i] : 0;
    s[t] = v;
    __syncthreads();
    #pragma unroll
    for (int off = 1; off < 256; off <<= 1) {
        int u = (t >= off) ? s[t - off] : 0;
        __syncthreads();
        s[t] += u;
        __syncthreads();
    }
    int incl = s[t];            // inclusive within block
    int agg = s[255];           // block aggregate

    if (t == 0) {
        if (b == 0) {
            atomicExch(&g_state[0], (2ull << 62) | (unsigned)agg);
            sbase = 0;
        } else {
            atomicExch(&g_state[b], (1ull << 62) | (unsigned)agg);
            int excl = 0;
            int j = b - 1;
            while (true) {
                u64 sj = atomicAdd(&g_state[j], 0ull);
                unsigned flag = (unsigned)(sj >> 62);
                if (flag == 0) continue;          // not published yet: spin
                excl += (int)(sj & 0xFFFFFFFFull);
                if (flag == 2u) break;            // inclusive prefix found
                --j;
            }
            atomicExch(&g_state[b], (2ull << 62) | (unsigned)(excl + agg));
            sbase = excl;
        }
    }
    __syncthreads();
    if (i < n) {
        g_rowptr[i] = sbase + incl - v;
        g_dinv[i] = rsqrtf((float)(v + 1));
    }
}

// Counting sort of src by dst. Bumps g_rowptr[d]; afterwards rowptr = row end.
__global__ void k_fill(const int* __restrict__ src,
                       const int* __restrict__ dst, int E) {
    int i = blockIdx.x * blockDim.x + threadIdx.x;
    int stride = gridDim.x * blockDim.x;
    int E4 = E >> 2;
    const int4* src4 = (const int4*)src;
    const int4* dst4 = (const int4*)dst;
    for (int j = i; j < E4; j += stride) {
        int4 s = src4[j];
        int4 d = dst4[j];
        g_csr[atomicAdd(&g_rowptr[d.x], 1)] = s.x;
        g_csr[atomicAdd(&g_rowptr[d.y], 1)] = s.y;
        g_csr[atomicAdd(&g_rowptr[d.z], 1)] = s.z;
        g_csr[atomicAdd(&g_rowptr[d.w], 1)] = s.w;
    }
    for (int j = (E4 << 2) + i; j < E; j += stride)
        g_csr[atomicAdd(&g_rowptr[dst[j]], 1)] = src[j];
}

// ---------------------------------------------------------------------------
// Tensor-core GEMM: 64x64 tile per block, 256 threads = 8 warps.
// Emits: fp16 table row = dinv[r]*acc, fp32 init = dinv[r]^2*acc + bias.
template<int K, bool RELU, bool READ_GH, bool STORE_GH>
__global__ void k_gemm(const float* __restrict__ Xp,
                       const float* __restrict__ W,
                       const float* __restrict__ bias,
                       float* __restrict__ outp,
                       int n)
{
    constexpr int SA = K + 8;
    constexpr int SB = 72;
    __shared__ __half As[64 * SA];
    __shared__ __half Bs[K * SB];

    const float* __restrict__ X = READ_GH ? (const float*)g_h : Xp;
    float* __restrict__ oinit = STORE_GH ? (float*)g_h : outp;
    __half* __restrict__ xwh = (__half*)g_xwh;

    int tid = threadIdx.x;
    int warp = tid >> 5;
    int lane = tid & 31;
    int row0 = blockIdx.x * 64;

    for (int i = tid; i < K * 64; i += 256) {
        int k = i >> 6, nn = i & 63;
        Bs[k * SB + nn] = __float2half_rn(W[i]);
    }
    {
        const int KQ = K / 4;
        for (int i = tid; i < 64 * KQ; i += 256) {
            int r = i / KQ;
            int k4 = (i - r * KQ) * 4;
            int rr = row0 + r;
            float4 v = make_float4(0.f, 0.f, 0.f, 0.f);
            if (rr < n)
                v = ((const float4*)X)[((size_t)rr * K + k4) >> 2];
            if (RELU) {
                v.x = fmaxf(v.x, 0.f); v.y = fmaxf(v.y, 0.f);
                v.z = fmaxf(v.z, 0.f); v.w = fmaxf(v.w, 0.f);
            }
            __half2* dst2 = (__half2*)&As[r * SA + k4];
            dst2[0] = __floats2half2_rn(v.x, v.y);
            dst2[1] = __floats2half2_rn(v.z, v.w);
        }
    }
    __syncthreads();

    const int wr = (warp & 3) * 16;
    const int wc = (warp >> 2) * 32;

    float d[4][4];
    #pragma unroll
    for (int f = 0; f < 4; ++f)
        #pragma unroll
        for (int i = 0; i < 4; ++i) d[f][i] = 0.f;

    unsigned baseA = s2u(&As[(wr + (lane & 15)) * SA + (lane >> 4) * 8]);
    unsigned baseB0 = s2u(&Bs[(lane & 15) * SB + wc + (lane >> 4) * 8]);
    unsigned baseB1 = s2u(&Bs[(lane & 15) * SB + wc + 16 + (lane >> 4) * 8]);

    #pragma unroll
    for (int k0 = 0; k0 < K; k0 += 16) {
        unsigned a[4], b[8];
        ldmx4 (a,     baseA  + k0 * 2);
        ldmx4t(b,     baseB0 + k0 * SB * 2);
        ldmx4t(b + 4, baseB1 + k0 * SB * 2);
        mma16816(d[0], a, b + 0);
        mma16816(d[1], a, b + 2);
        mma16816(d[2], a, b + 4);
        mma16816(d[3], a, b + 6);
    }

    int rA = row0 + wr + (lane >> 2);
    int rB = rA + 8;
    float diA = (rA < n) ? g_dinv[rA] : 0.f;
    float diB = (rB < n) ? g_dinv[rB] : 0.f;
    float sA = diA * diA, sB = diB * diB;
    #pragma unroll
    for (int f = 0; f < 4; ++f) {
        int c = wc + f * 8 + 2 * (lane & 3);
        float b0 = bias[c], b1 = bias[c + 1];
        if (rA < n) {
            *(__half2*)&xwh[(size_t)rA * 64 + c] =
                __floats2half2_rn(diA * d[f][0], diA * d[f][1]);
            float2 o2 = make_float2(fmaf(sA, d[f][0], b0), fmaf(sA, d[f][1], b1));
            *(float2*)&oinit[(size_t)rA * 64 + c] = o2;
        }
        if (rB < n) {
            *(__half2*)&xwh[(size_t)rB * 64 + c] =
                __floats2half2_rn(diB * d[f][2], diB * d[f][3]);
            float2 o2 = make_float2(fmaf(sB, d[f][2], b0), fmaf(sB, d[f][3], b1));
            *(float2*)&oinit[(size_t)rB * 64 + c] = o2;
        }
    }
}

// ---------------------------------------------------------------------------
// Gather aggregation: 8-lane group per node, lane owns 8 features.
// Messages pre-scaled by dinv[src] -> inner loop is pure adds; multiply by
// dinv[node] once at the end, then add the fp32 init row.
template<bool TO_GH>
__global__ void k_aggr(float4* __restrict__ outp, int n)
{
    float4* __restrict__ o = TO_GH ? g_h : outp;
    const uint4* __restrict__ xwh = g_xwh;

    int gtid = blockIdx.x * blockDim.x + threadIdx.x;
    int node = gtid >> 3;
    int lane = threadIdx.x & 7;
    if (node >= n) return;

    int end = g_rowptr[node];
    int deg = g_deg[node];
    int beg = end - deg;

    float acc[8];
    #pragma unroll
    for (int i = 0; i < 8; ++i) acc[i] = 0.f;

    #define ACC_EDGE(q) do {                                                 \
        float2 p0_ = h2f((q).x);                                             \
        float2 p1_ = h2f((q).y);                                             \
        float2 p2_ = h2f((q).z);                                             \
        float2 p3_ = h2f((q).w);                                             \
        acc[0] += p0_.x; acc[1] += p0_.y;                                    \
        acc[2] += p1_.x; acc[3] += p1_.y;                                    \
        acc[4] += p2_.x; acc[5] += p2_.y;                                    \
        acc[6] += p3_.x; acc[7] += p3_.y;                                    \
    } while (0)

    int e = beg;
    for (; e + 4 <= end; e += 4) {
        int s0 = g_csr[e];
        int s1 = g_csr[e + 1];
        int s2 = g_csr[e + 2];
        int s3 = g_csr[e + 3];
        uint4 q0 = __ldcg(xwh + (size_t)s0 * FU4 + lane);
        uint4 q1 = __ldcg(xwh + (size_t)s1 * FU4 + lane);
        uint4 q2 = __ldcg(xwh + (size_t)s2 * FU4 + lane);
        uint4 q3 = __ldcg(xwh + (size_t)s3 * FU4 + lane);
        ACC_EDGE(q0);
        ACC_EDGE(q1);
        ACC_EDGE(q2);
        ACC_EDGE(q3);
    }
    for (; e < end; ++e) {
        uint4 q = __ldcg(xwh + (size_t)g_csr[e] * FU4 + lane);
        ACC_EDGE(q);
    }
    #undef ACC_EDGE

    float dn = g_dinv[node];
    float4* p = o + (size_t)node * F4 + 2 * lane;
    float4 i0 = p[0];
    float4 i1 = p[1];
    i0.x = fmaf(dn, acc[0], i0.x); i0.y = fmaf(dn, acc[1], i0.y);
    i0.z = fmaf(dn, acc[2], i0.z); i0.w = fmaf(dn, acc[3], i0.w);
    i1.x = fmaf(dn, acc[4], i1.x); i1.y = fmaf(dn, acc[5], i1.y);
    i1.z = fmaf(dn, acc[6], i1.z); i1.w = fmaf(dn, acc[7], i1.w);
    p[0] = i0;
    p[1] = i1;
}

// ---------------------------------------------------------------------------
extern "C" void kernel_launch(void* const* d_in, const int* in_sizes, int n_in,
                              void* d_out, int out_size)
{
    const float* x  = (const float*)d_in[0];
    const int*   ei = (const int*)d_in[1];
    const float* W1 = (const float*)d_in[2];
    const float* b1 = (const float*)d_in[3];
    const float* W2 = (const float*)d_in[4];
    const float* b2 = (const float*)d_in[5];
    float* out = (float*)d_out;

    const int IN = 128;
    int N = in_sizes[0] / IN;
    int E = in_sizes[1] / 2;
    const int* src = ei;
    const int* dst = ei + E;

    int nb256 = (N + 255) / 256;
    int gemm_blocks = (N + 63) / 64;
    int edge_blocks = 1184;
    int aggr_blocks = (N + 31) / 32;

    // --- graph preprocessing ---
    void* degptr = nullptr;
    cudaGetSymbolAddress(&degptr, g_deg);
    cudaMemsetAsync(degptr, 0, (size_t)N * sizeof(int));
    k_deg_count<<<edge_blocks, 256>>>(dst, E);
    k_scan<<<nb256, 256>>>(N);
    k_fill<<<edge_blocks, 256>>>(src, dst, E);

    // --- layer 1: init rows -> g_h, aggregate into g_h ---
    k_gemm<128, false, false, true><<<gemm_blocks, 256>>>(x, W1, b1, nullptr, N);
    k_aggr<true><<<aggr_blocks, 256>>>(nullptr, N);

    // --- layer 2: init rows -> out, aggregate into out ---
    k_gemm<64, true, true, false><<<gemm_blocks, 256>>>(nullptr, W2, b2, out, N);
    k_aggr<false><<<aggr_blocks, 256>>>((float4*)out, N);
}